// round 14
// baseline (speedup 1.0000x reference)
#include <cuda_runtime.h>
#include <cuda_fp16.h>

#define N_NODES 50000
#define N_EDGES 1600000

// ---------------- scratch (device globals; no allocation allowed) ----------
__device__ uint2    g_WnH[N_NODES * 16];   // projected node features fp16
__device__ float4   g_dotS[N_NODES];       // a_s . Wn[n] per head
__device__ float4   g_dotR[N_NODES];       // a_r . Wn[n] per head
__device__ float4   g_ce4[16];             // c_e[h*4+q] = quad q of head h
__device__ unsigned g_cnt[N_NODES];        // in-degree histogram
__device__ unsigned g_ptr[N_NODES + 1];    // CSR row pointers (by receiver)
__device__ unsigned g_ptrw[N_NODES];       // working copy for scatter
__device__ unsigned g_scatS[N_EDGES];      // sender per CSR slot
__device__ float4   g_scatW[N_EDGES];      // per-head softmax weights per CSR slot

// ---------------- K0: zero histogram ----------------------------------------
__global__ void k_zero() {
    int i = blockIdx.x * 256 + threadIdx.x;
    if (i < N_NODES) g_cnt[i] = 0;
}

// ---------------- K1: receiver histogram ------------------------------------
__global__ void k_hist(const int* __restrict__ recv) {
    int e = blockIdx.x * 256 + threadIdx.x;   // 6250 blocks, exact
    atomicAdd(&g_cnt[recv[e]], 1u);
}

// ---------------- K2: exclusive scan (1 block) -------------------------------
__global__ void k_scan() {
    __shared__ unsigned sT[256];
    int t = threadIdx.x;
    int lo = t * 196;
    int hi = min(lo + 196, N_NODES);
    unsigned tot = 0;
    for (int i = lo; i < hi; i++) tot += g_cnt[i];
    sT[t] = tot;
    __syncthreads();
    for (int off = 1; off < 256; off <<= 1) {
        unsigned v = (t >= off) ? sT[t - off] : 0u;
        __syncthreads();
        sT[t] += v;
        __syncthreads();
    }
    unsigned run = (t > 0) ? sT[t - 1] : 0u;
    for (int i = lo; i < hi; i++) {
        unsigned c = g_cnt[i];
        g_ptr[i] = run;  g_ptrw[i] = run;
        run += c;
    }
    if (t == 255) g_ptr[N_NODES] = run;
}

// ---------------- K3: tiled GEMM node projection + dots + c_e ---------------
#define NSTR 68
__global__ void __launch_bounds__(256) k_node(const float* __restrict__ nodes,
                                              const float* __restrict__ W,
                                              const float* __restrict__ a,
                                              const float* __restrict__ We) {
    __shared__ __align__(16) float sW[64 * NSTR];
    __shared__ __align__(16) float sN[64 * NSTR];
    __shared__ float sA[192];

    int tid = threadIdx.x;
    int nb  = blockIdx.x * 64;

    if (blockIdx.x == 0 && tid < 64) {
        int h = tid >> 4, i = tid & 15;
        float acc = 0.f;
#pragma unroll
        for (int f = 0; f < 16; f++)
            acc += a[h * 48 + 32 + f] * We[h * 256 + f * 16 + i];
        ((float*)g_ce4)[tid] = acc;
    }

    float4 z4 = make_float4(0.f, 0.f, 0.f, 0.f);
#pragma unroll
    for (int g = tid; g < 1024; g += 256) {
        int row = g >> 4, q = g & 15;
        *(float4*)&sW[row * NSTR + q * 4] = ((const float4*)W)[g];
        int node = nb + row;
        *(float4*)&sN[row * NSTR + q * 4] =
            (node < N_NODES) ? ((const float4*)nodes)[(size_t)node * 16 + q] : z4;
    }
    if (tid < 192) sA[tid] = a[tid];
    __syncthreads();

    int jg = tid & 15, ng = tid >> 4;
    float acc[4][4];
#pragma unroll
    for (int nn = 0; nn < 4; nn++)
#pragma unroll
        for (int jj = 0; jj < 4; jj++) acc[nn][jj] = 0.f;

#pragma unroll
    for (int iq = 0; iq < 16; iq++) {
        float4 wv[4], nv[4];
#pragma unroll
        for (int jj = 0; jj < 4; jj++)
            wv[jj] = *(const float4*)&sW[(jg + jj * 16) * NSTR + iq * 4];
#pragma unroll
        for (int nn = 0; nn < 4; nn++)
            nv[nn] = *(const float4*)&sN[(ng + nn * 16) * NSTR + iq * 4];
#pragma unroll
        for (int nn = 0; nn < 4; nn++)
#pragma unroll
            for (int jj = 0; jj < 4; jj++)
                acc[nn][jj] += nv[nn].x * wv[jj].x + nv[nn].y * wv[jj].y
                             + nv[nn].z * wv[jj].z + nv[nn].w * wv[jj].w;
    }
    __syncthreads();

#pragma unroll
    for (int nn = 0; nn < 4; nn++)
#pragma unroll
        for (int jj = 0; jj < 4; jj++)
            sN[(ng + nn * 16) * NSTR + (jg + jj * 16)] = acc[nn][jj];
    __syncthreads();

    // fp16 Wn store
#pragma unroll
    for (int g = tid; g < 1024; g += 256) {
        int row = g >> 4, q = g & 15;
        int node = nb + row;
        if (node < N_NODES) {
            float4 v = *(const float4*)&sN[row * NSTR + q * 4];
            __half2 h0 = __floats2half2_rn(v.x, v.y);
            __half2 h1 = __floats2half2_rn(v.z, v.w);
            uint2 pk;
            pk.x = *(unsigned*)&h0;
            pk.y = *(unsigned*)&h1;
            g_WnH[(size_t)node * 16 + q] = pk;
        }
    }

    // dots: thread = (local node, head)
    {
        int n = tid >> 2, h = tid & 3;
        const float* row = &sN[n * NSTR + h * 16];
        float ds = 0.f, dr = 0.f;
#pragma unroll
        for (int f = 0; f < 16; f++) {
            ds += row[f] * sA[h * 48 + f];
            dr += row[f] * sA[h * 48 + 16 + f];
        }
        int node = nb + n;
        if (node < N_NODES) {
            ((float*)g_dotS)[(size_t)node * 4 + h] = ds;
            ((float*)g_dotR)[(size_t)node * 4 + h] = dr;
        }
    }
}

// ---------------- K4: fused weight-compute + CSR scatter ---------------------
// 4 lanes per edge (lane q owns feature quad q and head q's weight).
// 64 edges/block, 25,000 blocks exact. No red atomics - just the slot counter.
__global__ void __launch_bounds__(256) k_scw(const float* __restrict__ edges,
                                             const int* __restrict__ recv,
                                             const int* __restrict__ send) {
    __shared__ float4 sCe[16];
    if (threadIdx.x < 16) sCe[threadIdx.x] = g_ce4[threadIdx.x];
    __syncthreads();

    int tid = threadIdx.x;
    int q = tid & 3;
    int e = blockIdx.x * 64 + (tid >> 2);

    int s = send[e], r = recv[e];
    float4 ef = ((const float4*)edges)[(size_t)e * 4 + q];   // 64B/edge, coalesced

    float p[4];
#pragma unroll
    for (int h = 0; h < 4; h++) {
        float4 c = sCe[h * 4 + q];
        p[h] = ef.x * c.x + ef.y * c.y + ef.z * c.z + ef.w * c.w;
    }
#pragma unroll
    for (int h = 0; h < 4; h++) {
        p[h] += __shfl_xor_sync(0xffffffffu, p[h], 1, 4);
        p[h] += __shfl_xor_sync(0xffffffffu, p[h], 2, 4);
    }
    float ph = (q < 2) ? (q ? p[1] : p[0]) : ((q == 3) ? p[3] : p[2]);

    float m = ((const float*)g_dotS)[(size_t)s * 4 + q]
            + ((const float*)g_dotR)[(size_t)r * 4 + q] + ph;
    float w = __expf(m > 0.f ? m : 0.01f * m);

    float wa = __shfl_sync(0xffffffffu, w, 0, 4);
    float wb = __shfl_sync(0xffffffffu, w, 1, 4);
    float wc = __shfl_sync(0xffffffffu, w, 2, 4);
    float wd = __shfl_sync(0xffffffffu, w, 3, 4);

    if (q == 0) {
        unsigned pos = atomicAdd(&g_ptrw[r], 1u);
        g_scatS[pos] = (unsigned)s;
        g_scatW[pos] = make_float4(wa, wb, wc, wd);
    }
}

// ---------------- K5: per-receiver register aggregation + finalize -----------
// 16-lane group per receiver; walk its CSR range, accumulate in registers.
// Then self-edge + softmax normalize + ELU + LayerNorm, write out directly.
__global__ void __launch_bounds__(256) k_gather(const float* __restrict__ scale,
                                                const float* __restrict__ bias,
                                                float* __restrict__ out) {
    int lane = threadIdx.x & 31;
    int sub  = lane & 15;
    int h    = sub >> 2;
    int node = (blockIdx.x * 8 + (threadIdx.x >> 5)) * 2 + (lane >> 4);
    // 50000 = 3125 blocks * 8 warps * 2, exact

    unsigned beg = g_ptr[node], end = g_ptr[node + 1];

    float a0 = 0.f, a1 = 0.f, a2 = 0.f, a3 = 0.f, wsum = 0.f;
    unsigned i = beg;
    for (; i + 4 <= end; i += 4) {
        unsigned s0 = g_scatS[i],     s1 = g_scatS[i + 1];
        unsigned s2 = g_scatS[i + 2], s3 = g_scatS[i + 3];
        float4 w40 = g_scatW[i],     w41 = g_scatW[i + 1];
        float4 w42 = g_scatW[i + 2], w43 = g_scatW[i + 3];
        uint2 pk0 = g_WnH[(size_t)s0 * 16 + sub];
        uint2 pk1 = g_WnH[(size_t)s1 * 16 + sub];
        uint2 pk2 = g_WnH[(size_t)s2 * 16 + sub];
        uint2 pk3 = g_WnH[(size_t)s3 * 16 + sub];

        float w0 = (h < 2) ? (h ? w40.y : w40.x) : ((h == 3) ? w40.w : w40.z);
        float w1 = (h < 2) ? (h ? w41.y : w41.x) : ((h == 3) ? w41.w : w41.z);
        float w2 = (h < 2) ? (h ? w42.y : w42.x) : ((h == 3) ? w42.w : w42.z);
        float w3 = (h < 2) ? (h ? w43.y : w43.x) : ((h == 3) ? w43.w : w43.z);
        wsum += (w0 + w1) + (w2 + w3);

        float2 va, vb;
        va = __half22float2(*(__half2*)&pk0.x); vb = __half22float2(*(__half2*)&pk0.y);
        a0 += w0 * va.x; a1 += w0 * va.y; a2 += w0 * vb.x; a3 += w0 * vb.y;
        va = __half22float2(*(__half2*)&pk1.x); vb = __half22float2(*(__half2*)&pk1.y);
        a0 += w1 * va.x; a1 += w1 * va.y; a2 += w1 * vb.x; a3 += w1 * vb.y;
        va = __half22float2(*(__half2*)&pk2.x); vb = __half22float2(*(__half2*)&pk2.y);
        a0 += w2 * va.x; a1 += w2 * va.y; a2 += w2 * vb.x; a3 += w2 * vb.y;
        va = __half22float2(*(__half2*)&pk3.x); vb = __half22float2(*(__half2*)&pk3.y);
        a0 += w3 * va.x; a1 += w3 * va.y; a2 += w3 * vb.x; a3 += w3 * vb.y;
    }
    for (; i < end; i++) {
        unsigned s0 = g_scatS[i];
        float4 w40 = g_scatW[i];
        uint2 pk0 = g_WnH[(size_t)s0 * 16 + sub];
        float w0 = (h < 2) ? (h ? w40.y : w40.x) : ((h == 3) ? w40.w : w40.z);
        wsum += w0;
        float2 va = __half22float2(*(__half2*)&pk0.x);
        float2 vb = __half22float2(*(__half2*)&pk0.y);
        a0 += w0 * va.x; a1 += w0 * va.y; a2 += w0 * vb.x; a3 += w0 * vb.y;
    }

    // self edge (zero features)
    float ms = ((const float*)g_dotS)[(size_t)node * 4 + h]
             + ((const float*)g_dotR)[(size_t)node * 4 + h];
    float ws = __expf(ms > 0.f ? ms : 0.01f * ms);
    {
        uint2 pk = g_WnH[(size_t)node * 16 + sub];
        float2 va = __half22float2(*(__half2*)&pk.x);
        float2 vb = __half22float2(*(__half2*)&pk.y);
        a0 += ws * va.x; a1 += ws * va.y; a2 += ws * vb.x; a3 += ws * vb.y;
        wsum += ws;
    }

    float inv_nm = 1.0f / wsum;
    float x0 = a0 * inv_nm, x1 = a1 * inv_nm, x2 = a2 * inv_nm, x3 = a3 * inv_nm;
    float y0 = x0 > 0.f ? x0 : expm1f(x0);
    float y1 = x1 > 0.f ? x1 : expm1f(x1);
    float y2 = x2 > 0.f ? x2 : expm1f(x2);
    float y3 = x3 > 0.f ? x3 : expm1f(x3);

    float sum = y0 + y1 + y2 + y3;
#pragma unroll
    for (int mm = 8; mm >= 1; mm >>= 1) sum += __shfl_xor_sync(0xffffffffu, sum, mm, 16);
    float mean = sum * (1.0f / 64.0f);

    float d0 = y0 - mean, d1 = y1 - mean, d2 = y2 - mean, d3 = y3 - mean;
    float v = d0 * d0 + d1 * d1 + d2 * d2 + d3 * d3;
#pragma unroll
    for (int mm = 8; mm >= 1; mm >>= 1) v += __shfl_xor_sync(0xffffffffu, v, mm, 16);
    float inv = rsqrtf(v * (1.0f / 64.0f) + 1e-6f);

    float4 sc = ((const float4*)scale)[sub];
    float4 bi = ((const float4*)bias)[sub];
    float4 o;
    o.x = d0 * inv * sc.x + bi.x;
    o.y = d1 * inv * sc.y + bi.y;
    o.z = d2 * inv * sc.z + bi.z;
    o.w = d3 * inv * sc.w + bi.w;
    ((float4*)out)[(size_t)node * 16 + sub] = o;
}

// ---------------- launch -----------------------------------------------------
extern "C" void kernel_launch(void* const* d_in, const int* in_sizes, int n_in,
                              void* d_out, int out_size) {
    const float* nodes   = (const float*)d_in[0];
    const float* edges   = (const float*)d_in[1];
    const int*   recv    = (const int*)d_in[2];
    const int*   send    = (const int*)d_in[3];
    const float* W       = (const float*)d_in[4];
    const float* W_edge  = (const float*)d_in[5];
    const float* a       = (const float*)d_in[6];
    const float* ln_s    = (const float*)d_in[7];
    const float* ln_b    = (const float*)d_in[8];
    float* out = (float*)d_out;

    k_zero<<<196, 256>>>();
    k_hist<<<N_EDGES / 256, 256>>>(recv);                       // 6250 blocks
    k_scan<<<1, 256>>>();
    k_node<<<(N_NODES + 63) / 64, 256>>>(nodes, W, a, W_edge);  // 782 blocks
    k_scw<<<N_EDGES / 64, 256>>>(edges, recv, send);            // 25,000 blocks
    k_gather<<<N_NODES / 16, 256>>>(ln_s, ln_b, out);           // 3125 blocks
}

// round 17
// speedup vs baseline: 1.6022x; 1.6022x over previous
#include <cuda_runtime.h>
#include <cuda_fp16.h>

#define N_NODES 50000
#define N_EDGES 1600000

// ---------------- scratch (device globals; no allocation allowed) ----------
__device__ uint2  g_WnH[N_NODES * 16];    // projected node features fp16
__device__ float4 g_dotS[N_NODES];        // a_s . Wn[n]  per head (fp32)
__device__ float4 g_dotR[N_NODES];        // a_r . Wn[n]  per head (fp32)
__device__ float4 g_norm[N_NODES];        // softmax denominator per head (excl. self edge)
__device__ float4 g_aggr[N_NODES * 16];   // weighted sum [N,64] (excl. self edge)
__device__ float4 g_ce4[16];              // c_e as float4: g_ce4[h*4+q] = c_h[4q..4q+3]

__device__ __forceinline__ void red_add_v4(float4* addr, float x, float y, float z, float w) {
    asm volatile("red.global.add.v4.f32 [%0], {%1, %2, %3, %4};"
                 :: "l"(addr), "f"(x), "f"(y), "f"(z), "f"(w) : "memory");
}
__device__ __forceinline__ void red_add_f32(float* addr, float v) {
    asm volatile("red.global.add.f32 [%0], %1;" :: "l"(addr), "f"(v) : "memory");
}
// streaming (evict-first) loads for one-pass data
__device__ __forceinline__ int ldcs_i32(const int* p) { return __ldcs(p); }
__device__ __forceinline__ float4 ldcs_f4(const float4* p) { return __ldcs(p); }

// ---------------- K2: tiled GEMM node projection + dots + zero + c_e --------
#define NSTR 68
__global__ void __launch_bounds__(256, 4) k_node(const float* __restrict__ nodes,
                                                 const float* __restrict__ W,
                                                 const float* __restrict__ a,
                                                 const float* __restrict__ We) {
    __shared__ __align__(16) float sW[64 * NSTR];
    __shared__ __align__(16) float sN[64 * NSTR];   // input tile, then output tile
    __shared__ float sA[192];

    int tid = threadIdx.x;
    int nb  = blockIdx.x * 64;

    if (blockIdx.x == 0 && tid < 64) {              // c_e fold (once)
        int h = tid >> 4, i = tid & 15;
        float acc = 0.f;
#pragma unroll
        for (int f = 0; f < 16; f++)
            acc += a[h * 48 + 32 + f] * We[h * 256 + f * 16 + i];
        ((float*)g_ce4)[tid] = acc;
    }

    float4 z4 = make_float4(0.f, 0.f, 0.f, 0.f);
#pragma unroll
    for (int g = tid; g < 1024; g += 256) {
        int row = g >> 4, q = g & 15;
        *(float4*)&sW[row * NSTR + q * 4] = ((const float4*)W)[g];
        int node = nb + row;
        *(float4*)&sN[row * NSTR + q * 4] =
            (node < N_NODES) ? ((const float4*)nodes)[(size_t)node * 16 + q] : z4;
        if (node < N_NODES) g_aggr[(size_t)node * 16 + q] = z4;
    }
    if (tid < 192) sA[tid] = a[tid];
    if (tid < 64 && nb + tid < N_NODES) g_norm[nb + tid] = z4;
    __syncthreads();

    int jg = tid & 15, ng = tid >> 4;
    float acc[4][4];
#pragma unroll
    for (int nn = 0; nn < 4; nn++)
#pragma unroll
        for (int jj = 0; jj < 4; jj++) acc[nn][jj] = 0.f;

#pragma unroll
    for (int iq = 0; iq < 16; iq++) {
        float4 wv[4], nv[4];
#pragma unroll
        for (int jj = 0; jj < 4; jj++)
            wv[jj] = *(const float4*)&sW[(jg + jj * 16) * NSTR + iq * 4];
#pragma unroll
        for (int nn = 0; nn < 4; nn++)
            nv[nn] = *(const float4*)&sN[(ng + nn * 16) * NSTR + iq * 4];
#pragma unroll
        for (int nn = 0; nn < 4; nn++)
#pragma unroll
            for (int jj = 0; jj < 4; jj++)
                acc[nn][jj] += nv[nn].x * wv[jj].x + nv[nn].y * wv[jj].y
                             + nv[nn].z * wv[jj].z + nv[nn].w * wv[jj].w;
    }
    __syncthreads();

#pragma unroll
    for (int nn = 0; nn < 4; nn++)
#pragma unroll
        for (int jj = 0; jj < 4; jj++)
            sN[(ng + nn * 16) * NSTR + (jg + jj * 16)] = acc[nn][jj];
    __syncthreads();

    // fp16 Wn store
#pragma unroll
    for (int g = tid; g < 1024; g += 256) {
        int row = g >> 4, q = g & 15;
        int node = nb + row;
        if (node < N_NODES) {
            float4 v = *(const float4*)&sN[row * NSTR + q * 4];
            __half2 h0 = __floats2half2_rn(v.x, v.y);
            __half2 h1 = __floats2half2_rn(v.z, v.w);
            uint2 pk;
            pk.x = *(unsigned*)&h0;
            pk.y = *(unsigned*)&h1;
            g_WnH[(size_t)node * 16 + q] = pk;
        }
    }

    // dots from fp32 smem tile: thread = (local node, head)
    {
        int n = tid >> 2, h = tid & 3;
        const float* row = &sN[n * NSTR + h * 16];
        float ds = 0.f, dr = 0.f;
#pragma unroll
        for (int f = 0; f < 16; f++) {
            ds += row[f] * sA[h * 48 + f];
            dr += row[f] * sA[h * 48 + 16 + f];
        }
        int node = nb + n;
        if (node < N_NODES) {
            ((float*)g_dotS)[(size_t)node * 4 + h] = ds;
            ((float*)g_dotR)[(size_t)node * 4 + h] = dr;
        }
    }
}

// ---------------- K3: fused edge pass, 8 edges/warp (4x ILP) -----------------
// 16 lanes per edge-slot; each 16-lane group handles 4 edges with strictly
// stage-batched loads. Streaming loads (__ldcs) on the one-pass edge data keep
// the hot WnH/dot/aggr working set resident in L2.
// 1.6M edges = 25,000 blocks * 8 warps * 8 edges exactly: no bounds checks.
__global__ void __launch_bounds__(256) k_edge(const float* __restrict__ edges,
                                              const int* __restrict__ recv,
                                              const int* __restrict__ send) {
    int lane = threadIdx.x & 31;
    int sub  = lane & 15;
    int h    = sub >> 2;
    int q    = sub & 3;
    int base = (blockIdx.x * 8 + (threadIdx.x >> 5)) * 8 + (lane >> 4);

    float4 c4 = g_ce4[sub];
    const float* dSf = (const float*)g_dotS;
    const float* dRf = (const float*)g_dotR;

    // stage 1: all index loads (streaming)
    int s[4], r[4];
#pragma unroll
    for (int k = 0; k < 4; k++) {
        int e = base + 2 * k;
        s[k] = ldcs_i32(send + e);
        r[k] = ldcs_i32(recv + e);
    }

    // stage 2: all edge-feature loads (streaming) + partial dots
    float p[4];
#pragma unroll
    for (int k = 0; k < 4; k++) {
        float4 ef = ldcs_f4((const float4*)edges + (size_t)(base + 2 * k) * 4 + q);
        p[k] = ef.x * c4.x + ef.y * c4.y + ef.z * c4.z + ef.w * c4.w;
    }
#pragma unroll
    for (int k = 0; k < 4; k++) {
        p[k] += __shfl_xor_sync(0xffffffffu, p[k], 1, 4);
        p[k] += __shfl_xor_sync(0xffffffffu, p[k], 2, 4);
    }

    // stage 3: all dot loads (batched before use)
    float dsv[4], drv[4];
#pragma unroll
    for (int k = 0; k < 4; k++) dsv[k] = dSf[(size_t)s[k] * 4 + h];
#pragma unroll
    for (int k = 0; k < 4; k++) drv[k] = dRf[(size_t)r[k] * 4 + h];

    // stage 4: all Wn gathers (batched)
    uint2 pk[4];
#pragma unroll
    for (int k = 0; k < 4; k++) pk[k] = g_WnH[(size_t)s[k] * 16 + sub];

    // stage 5: weights
    float w[4];
#pragma unroll
    for (int k = 0; k < 4; k++) {
        float m = dsv[k] + drv[k] + p[k];
        w[k] = __expf(m > 0.f ? m : 0.01f * m);
    }

    // stage 6: reductions
#pragma unroll
    for (int k = 0; k < 4; k++) {
        if (q == 0) red_add_f32((float*)&g_norm[r[k]] + h, w[k]);
        float2 va = __half22float2(*(__half2*)&pk[k].x);
        float2 vb = __half22float2(*(__half2*)&pk[k].y);
        red_add_v4(&g_aggr[(size_t)r[k] * 16 + sub],
                   va.x * w[k], va.y * w[k], vb.x * w[k], vb.y * w[k]);
    }
}

// ---------------- K4: self-edge + normalize + ELU + LayerNorm ----------------
__global__ void k_final(const float* __restrict__ scale,
                        const float* __restrict__ bias,
                        float* __restrict__ out) {
    int lane = threadIdx.x & 31;
    int sub  = lane & 15;
    int h    = sub >> 2;
    int node = (blockIdx.x * 8 + (threadIdx.x >> 5)) * 2 + (lane >> 4);

    float ms = ((const float*)g_dotS)[(size_t)node * 4 + h]
             + ((const float*)g_dotR)[(size_t)node * 4 + h];
    float ws = __expf(ms > 0.f ? ms : 0.01f * ms);

    uint2 pk = g_WnH[(size_t)node * 16 + sub];
    float2 va = __half22float2(*(__half2*)&pk.x);
    float2 vb = __half22float2(*(__half2*)&pk.y);

    float4 ag = g_aggr[(size_t)node * 16 + sub];
    float  nm = ((const float*)&g_norm[node])[h] + ws;
    float inv_nm = 1.0f / nm;

    float x0 = (ag.x + ws * va.x) * inv_nm;
    float x1 = (ag.y + ws * va.y) * inv_nm;
    float x2 = (ag.z + ws * vb.x) * inv_nm;
    float x3 = (ag.w + ws * vb.y) * inv_nm;
    float y0 = x0 > 0.f ? x0 : expm1f(x0);
    float y1 = x1 > 0.f ? x1 : expm1f(x1);
    float y2 = x2 > 0.f ? x2 : expm1f(x2);
    float y3 = x3 > 0.f ? x3 : expm1f(x3);

    float sum = y0 + y1 + y2 + y3;
#pragma unroll
    for (int m = 8; m >= 1; m >>= 1) sum += __shfl_xor_sync(0xffffffffu, sum, m, 16);
    float mean = sum * (1.0f / 64.0f);

    float d0 = y0 - mean, d1 = y1 - mean, d2 = y2 - mean, d3 = y3 - mean;
    float v = d0 * d0 + d1 * d1 + d2 * d2 + d3 * d3;
#pragma unroll
    for (int m = 8; m >= 1; m >>= 1) v += __shfl_xor_sync(0xffffffffu, v, m, 16);
    float inv = rsqrtf(v * (1.0f / 64.0f) + 1e-6f);

    float4 sc = ((const float4*)scale)[sub];
    float4 bi = ((const float4*)bias)[sub];
    float4 o;
    o.x = d0 * inv * sc.x + bi.x;
    o.y = d1 * inv * sc.y + bi.y;
    o.z = d2 * inv * sc.z + bi.z;
    o.w = d3 * inv * sc.w + bi.w;
    ((float4*)out)[(size_t)node * 16 + sub] = o;
}

// ---------------- launch -----------------------------------------------------
extern "C" void kernel_launch(void* const* d_in, const int* in_sizes, int n_in,
                              void* d_out, int out_size) {
    const float* nodes   = (const float*)d_in[0];
    const float* edges   = (const float*)d_in[1];
    const int*   recv    = (const int*)d_in[2];
    const int*   send    = (const int*)d_in[3];
    const float* W       = (const float*)d_in[4];
    const float* W_edge  = (const float*)d_in[5];
    const float* a       = (const float*)d_in[6];
    const float* ln_s    = (const float*)d_in[7];
    const float* ln_b    = (const float*)d_in[8];
    float* out = (float*)d_out;

    k_node<<<(N_NODES + 63) / 64, 256>>>(nodes, W, a, W_edge);  // 782 blocks
    k_edge<<<N_EDGES / 64, 256>>>(edges, recv, send);           // 25,000 blocks, 8 edges/warp
    k_final<<<N_NODES / 16, 256>>>(ln_s, ln_b, out);            // 3125 blocks, exact
}